// round 5
// baseline (speedup 1.0000x reference)
#include <cuda_runtime.h>

// DeEmphasis: y[n] = x[n] + ALPHA*y[n-1], zero init, rows of 960000 fp32.
//
// R3: single-wave persistent warps. Carry propagates exactly within a warp's
// contiguous span, so spans can be long: 74 warps per row x 64 rows = 4736
// warps = 148 SMs x 8 blocks x 4 warps -> exactly ONE wave, no tail.
// Each warp owns ~101-102 groups of 128 elems; halo = 1 group (alpha^128 ~
// 9.2e-10, below any meaningful error) paid once per warp (1% overhead).
// Per group: lane holds float4 (coalesced 512B), 3-FMA local scan, 5-step
// warp Kogge-Stone affine scan (coef alpha^4), recompute outputs from true
// entering state, float4 store. 4-wide unrolled body for MLP/ILP.

#define ALPHA 0.85f

static constexpr int ROWLEN = 960000;
static constexpr int GPR    = ROWLEN / 128;   // 7500 groups per row
static constexpr int WPR    = 74;             // warps per row (148 SMs / 2)
static constexpr int WPB    = 4;              // warps per block
static constexpr int THREADS = WPB * 32;      // 128

// compile-time alpha^n (double accumulation, rounded once)
__host__ __device__ constexpr float apow(int n) {
    double r = 1.0;
    for (int i = 0; i < n; i++) r *= (double)ALPHA;
    return (float)r;
}

// Process one 128-element group (4 consecutive elems per lane).
// c: warp-entering filter state (updated). Returns the 4 outputs.
__device__ __forceinline__ float4 proc128(float4 v, float AL, float& c, int lane)
{
    const float A    = ALPHA;
    const float A4   = apow(4);
    const float A128 = apow(128);

    // local inclusive scan of the lane's 4 elements (zero entering)
    float l1 = fmaf(A, v.x, v.y);
    float l2 = fmaf(A, l1, v.z);
    float l3 = fmaf(A, l2, v.w);

    // warp Kogge-Stone affine scan over lane totals, per-lane coef alpha^4
    float s = l3, cp = A4;
    #pragma unroll
    for (int d = 1; d < 32; d <<= 1) {
        float u = __shfl_up_sync(0xffffffffu, s, d);
        if (lane >= d) s = fmaf(cp, u, s);
        cp *= cp;
    }
    float wtot = __shfl_sync(0xffffffffu, s, 31);     // warp total (zero entry)
    float e    = __shfl_up_sync(0xffffffffu, s, 1);   // state entering my 4-seg
    if (lane == 0) e = 0.0f;

    // true entering state for this lane's segment: e + alpha^(4*lane) * c
    float enter = fmaf(AL, c, e);

    float4 o;
    o.x = fmaf(A, enter, v.x);
    o.y = fmaf(A, o.x,  v.y);
    o.z = fmaf(A, o.y,  v.z);
    o.w = fmaf(A, o.z,  v.w);

    c = fmaf(A128, c, wtot);    // carry into next 128-group
    return o;
}

__global__ void __launch_bounds__(THREADS, 8)
deemph_kernel(const float* __restrict__ x, float* __restrict__ y, int nwarps)
{
    const int gw = blockIdx.x * WPB + (threadIdx.x >> 5);
    if (gw >= nwarps) return;
    const int lane = threadIdx.x & 31;
    const int row  = gw / WPR;
    const int w    = gw - row * WPR;

    // this warp owns groups [g0, g1) of its row (balanced split of 7500/74)
    const int g0 = (w * GPR) / WPR;
    const int g1 = ((w + 1) * GPR) / WPR;

    // per-lane constant alpha^(4*lane) via 5 conditional multiplies
    float AL = 1.0f;
    if (lane & 1)  AL *= apow(4);
    if (lane & 2)  AL *= apow(8);
    if (lane & 4)  AL *= apow(16);
    if (lane & 8)  AL *= apow(32);
    if (lane & 16) AL *= apow(64);

    const float* px = x + row * ROWLEN + lane * 4;
    float*       py = y + row * ROWLEN + lane * 4;

    float c = 0.0f;

    // halo warm-up: one group before g0 (w==0 has true zero history)
    if (w > 0) {
        float4 h = __ldcs((const float4*)(px + (g0 - 1) * 128));
        (void)proc128(h, AL, c, lane);
    }

    int g = g0;

    // main: 4-wide batches (independent loads + independent shfl chains)
    #pragma unroll 1
    for (; g + 4 <= g1; g += 4) {
        const float* p = px + g * 128;
        float4 v0 = __ldcs((const float4*)(p));
        float4 v1 = __ldcs((const float4*)(p + 128));
        float4 v2 = __ldcs((const float4*)(p + 256));
        float4 v3 = __ldcs((const float4*)(p + 384));

        float4 o0 = proc128(v0, AL, c, lane);
        float4 o1 = proc128(v1, AL, c, lane);
        float4 o2 = proc128(v2, AL, c, lane);
        float4 o3 = proc128(v3, AL, c, lane);

        float* q = py + g * 128;
        __stcs((float4*)(q),       o0);
        __stcs((float4*)(q + 128), o1);
        __stcs((float4*)(q + 256), o2);
        __stcs((float4*)(q + 384), o3);
    }

    // remainder groups (0-3)
    #pragma unroll 1
    for (; g < g1; g++) {
        float4 v = __ldcs((const float4*)(px + g * 128));
        float4 o = proc128(v, AL, c, lane);
        __stcs((float4*)(py + g * 128), o);
    }
}

extern "C" void kernel_launch(void* const* d_in, const int* in_sizes, int n_in,
                              void* d_out, int out_size)
{
    const float* x = (const float*)d_in[0];
    float*       y = (float*)d_out;

    const int n      = in_sizes[0];          // 61,440,000
    const int rows   = n / ROWLEN;           // 64
    const int nwarps = rows * WPR;           // 4736 = 148 * 8 * 4
    const int blocks = (nwarps + WPB - 1) / WPB;   // 1184 = 148 * 8

    deemph_kernel<<<blocks, THREADS>>>(x, y, nwarps);
}